// round 2
// baseline (speedup 1.0000x reference)
#include <cuda_runtime.h>
#include <math.h>

// out[b,c,h,w] = prod_{p=1..24} cos(x_patch[p] + w[p]),  p = di*5+dj, 5x5 'same' window.
// Identity: cos(x+w_p) = cos(x)*cos(w_p) - sin(x)*sin(w_p).
// Per plane (64x64): smem tile of (cos x, sin x) with 2-halo; padded cells -> (1,0).

#define HW   64
#define PLANE (HW * HW)
#define TW   68   // 64 + 2*2 halo

__global__ __launch_bounds__(256, 3)
void quanv_kernel(const float* __restrict__ x,
                  const float* __restrict__ w,
                  float* __restrict__ out)
{
    __shared__ float2 scs[TW][TW];   // (cos, sin) of padded pixel

    const int plane = blockIdx.x;
    const float* xp = x + (size_t)plane * PLANE;
    float* op = out + (size_t)plane * PLANE;
    const int tid = threadIdx.x;

    // Weights -> registers (fully unrolled, compile-time indexed after unroll).
    float cw[25], sw[25];
#pragma unroll
    for (int p = 0; p < 25; ++p) {
        sincosf(__ldg(&w[p]), &sw[p], &cw[p]);
    }

    // Load 68x68 halo tile, compute per-pixel sincos.
    for (int idx = tid; idx < TW * TW; idx += 256) {
        const int i = idx / TW;
        const int j = idx - i * TW;
        const int gi = i - 2;
        const int gj = j - 2;
        float v = 0.0f;
        if ((unsigned)gi < (unsigned)HW && (unsigned)gj < (unsigned)HW)
            v = xp[gi * HW + gj];
        float s, c;
        sincosf(v, &s, &c);
        scs[i][j] = make_float2(c, s);
    }
    __syncthreads();

    // Each thread: 8 vertical output pairs (rows i and i+1) at a fixed column j.
    // Lane-consecutive j -> conflict-free LDS.64. Vertical pair shares 20/30 pixels.
    const int j  = tid & 63;          // 0..63
    const int i0 = (tid >> 6) * 2;    // 0,2,4,6

#pragma unroll
    for (int r = 0; r < 8; ++r) {
        const int i = i0 + r * 8;     // even row; pair covers rows i, i+1
        float pa = 1.0f, pb = 1.0f;

#pragma unroll
        for (int di = 0; di < 6; ++di) {
#pragma unroll
            for (int dj = 0; dj < 5; ++dj) {
                const float2 v = scs[i + di][j + dj];
                // Output A (row i): patch row di (0..4), weight p = di*5+dj, skip p==0.
                if (di < 5 && (di + dj > 0)) {
                    const int p = di * 5 + dj;
                    pa *= fmaf(v.x, cw[p], -v.y * sw[p]);
                }
                // Output B (row i+1): patch row di-1 (0..4), weight p=(di-1)*5+dj, skip p==0.
                if (di >= 1 && ((di - 1) + dj > 0)) {
                    const int p = (di - 1) * 5 + dj;
                    pb *= fmaf(v.x, cw[p], -v.y * sw[p]);
                }
            }
        }
        op[i * HW + j]       = pa;
        op[(i + 1) * HW + j] = pb;
    }
}

extern "C" void kernel_launch(void* const* d_in, const int* in_sizes, int n_in,
                              void* d_out, int out_size)
{
    const float* x = (const float*)d_in[0];
    const float* w = (const float*)d_in[1];
    float* out = (float*)d_out;

    const int planes = in_sizes[0] / PLANE;   // B*C = 512 for the reference shape
    quanv_kernel<<<planes, 256>>>(x, w, out);
}

// round 3
// speedup vs baseline: 1.1316x; 1.1316x over previous
#include <cuda_runtime.h>
#include <math.h>

// out[b,c,h,w] = prod_{p=1..24} cos(x_p + w_p) over the 5x5 'same' window.
// cos(x+w_p) = cos(w_p) * (cos x - tan(w_p) * sin x)
// => out = scale * prod_{p=1..24} (c - t_p * s),  scale = prod cos(w_p), t_p = tan(w_p).
// One FFMA per factor; scale hoisted. Per-pixel (c,s) via MUFU __sincosf in a
// 68x68 halo smem tile; padded cells -> (1,0) giving factor 1 - t*0... wait:
// padded factor must be cos(0+w_p)=cw_p -> (c,s)=(1,0) gives (1 - t*0)=1, and the
// hoisted scale already contributes cw_p. Correct.

#define HW    64
#define PLANE (HW * HW)
#define TW    68   // 64 + 2*2 halo

__device__ float g_t[25];    // tan(w_p); p=0 unused
__device__ float g_scale;    // prod_{p=1..24} cos(w_p)

__global__ void prep_kernel(const float* __restrict__ w)
{
    __shared__ float cwsh[25];
    const int p = threadIdx.x;
    if (p < 25) {
        float s, c;
        sincosf(w[p], &s, &c);   // accurate; only 25 values
        g_t[p]  = s / c;
        cwsh[p] = c;
    }
    __syncwarp();
    if (p == 0) {
        float sc = 1.0f;
#pragma unroll
        for (int q = 1; q < 25; ++q) sc *= cwsh[q];
        g_scale = sc;
    }
}

__global__ __launch_bounds__(256, 4)
void quanv_kernel(const float* __restrict__ x,
                  float* __restrict__ out)
{
    __shared__ float2 scs[TW][TW];   // (cos x, sin x) of padded pixel

    const int plane = blockIdx.x;
    const float* xp = x + (size_t)plane * PLANE;
    float* op = out + (size_t)plane * PLANE;
    const int tid = threadIdx.x;

    // tan(w_p) -> registers (compile-time indexed after full unroll).
    float t[25];
#pragma unroll
    for (int p = 1; p < 25; ++p) t[p] = g_t[p];
    const float scale = g_scale;

    // Build 68x68 halo tile of (cos, sin) with MUFU sincos.
    for (int idx = tid; idx < TW * TW; idx += 256) {
        const int i = idx / TW;
        const int j = idx - i * TW;
        const int gi = i - 2;
        const int gj = j - 2;
        float v = 0.0f;
        if ((unsigned)gi < (unsigned)HW && (unsigned)gj < (unsigned)HW)
            v = xp[gi * HW + gj];
        float s, c;
        __sincosf(v, &s, &c);
        scs[i][j] = make_float2(c, s);
    }
    __syncthreads();

    // Each thread: 8 vertical output pairs (rows i, i+1) at fixed column j.
    // Lane-consecutive j -> conflict-free LDS.64; pair shares 20/30 tile loads.
    const int j  = tid & 63;          // 0..63
    const int i0 = (tid >> 6) * 2;    // 0,2,4,6

#pragma unroll
    for (int r = 0; r < 8; ++r) {
        const int i = i0 + r * 8;     // pair covers output rows i, i+1

        // 4-way product trees per output -> 8 independent FMUL chains.
        float a0 = 1.0f, a1 = 1.0f, a2 = 1.0f, a3 = 1.0f;
        float b0 = 1.0f, b1 = 1.0f, b2 = 1.0f, b3 = 1.0f;

#pragma unroll
        for (int di = 0; di < 6; ++di) {
#pragma unroll
            for (int dj = 0; dj < 5; ++dj) {
                const float2 v = scs[i + di][j + dj];
                // Output A (row i): weight p = di*5+dj, p>=1, di in 0..4.
                if (di < 5 && (di + dj > 0)) {
                    const int p = di * 5 + dj;
                    const float f = fmaf(-t[p], v.y, v.x);
                    const int k = (p - 1) & 3;
                    if (k == 0) a0 *= f;
                    else if (k == 1) a1 *= f;
                    else if (k == 2) a2 *= f;
                    else a3 *= f;
                }
                // Output B (row i+1): weight p = (di-1)*5+dj, p>=1, di in 1..5.
                if (di >= 1 && ((di - 1) + dj > 0)) {
                    const int p = (di - 1) * 5 + dj;
                    const float f = fmaf(-t[p], v.y, v.x);
                    const int k = (p - 1) & 3;
                    if (k == 0) b0 *= f;
                    else if (k == 1) b1 *= f;
                    else if (k == 2) b2 *= f;
                    else b3 *= f;
                }
            }
        }
        op[i * HW + j]       = ((a0 * a1) * (a2 * a3)) * scale;
        op[(i + 1) * HW + j] = ((b0 * b1) * (b2 * b3)) * scale;
    }
}

extern "C" void kernel_launch(void* const* d_in, const int* in_sizes, int n_in,
                              void* d_out, int out_size)
{
    const float* x = (const float*)d_in[0];
    const float* w = (const float*)d_in[1];
    float* out = (float*)d_out;

    const int planes = in_sizes[0] / PLANE;   // B*C = 512

    prep_kernel<<<1, 32>>>(w);
    quanv_kernel<<<planes, 256>>>(x, out);
}

// round 4
// speedup vs baseline: 1.6794x; 1.4841x over previous
#include <cuda_runtime.h>
#include <math.h>

// out[b,c,h,w] = prod_{p=1..24} cos(x_p + w_p) over the 5x5 'same' window.
// cos(x+w_p) = cos(w_p) * (cos x - tan(w_p) * sin x)
// => out = scale * prod_{p>=1} (c - t_p * s).
// Sliding-window form: H_di(r,j) = prod_dj (c - t[di*5+dj]*s) over row r;
// out(i,j) = scale * prod_di H_di(i+di, j).  One thread per column walks rows,
// computes all 5 variants of each row once, multiplies into 5 pending outputs.

#define HW    64
#define PLANE (HW * HW)
#define TW    68   // 64 + 2*2 col halo
#define TR    36   // 32 output rows + 2*2 row halo

__device__ float g_t[25];    // tan(w_p); p=0 unused
__device__ float g_scale;    // prod_{p=1..24} cos(w_p)

__global__ void prep_kernel(const float* __restrict__ w)
{
    __shared__ float cwsh[25];
    const int p = threadIdx.x;
    if (p < 25) {
        float s, c;
        sincosf(w[p], &s, &c);   // accurate; only 25 values
        g_t[p]  = s / c;
        cwsh[p] = c;
    }
    __syncwarp();
    if (p == 0) {
        float sc = 1.0f;
#pragma unroll
        for (int q = 1; q < 25; ++q) sc *= cwsh[q];
        g_scale = sc;
    }
}

__global__ __launch_bounds__(128, 8)
void quanv_kernel(const float* __restrict__ x,
                  float* __restrict__ out)
{
    __shared__ float2 scs[TR][TW];   // (cos x, sin x); padded cells -> (1,0)

    const int blk   = blockIdx.x;
    const int plane = blk >> 1;
    const int base  = (blk & 1) * 32;          // first output row of this half
    const float* xp = x + (size_t)plane * PLANE;
    float* op = out + (size_t)plane * PLANE;
    const int tid = threadIdx.x;

    // tan(w_p) -> registers (compile-time indexed after unroll).
    float t[25];
#pragma unroll
    for (int p = 1; p < 25; ++p) t[p] = g_t[p];
    const float scale = g_scale;

    // Build 36x68 halo tile: tile row 0 = global row base-2, tile col 0 = global col -2.
    for (int idx = tid; idx < TR * TW; idx += 128) {
        const int i  = idx / TW;
        const int j  = idx - i * TW;
        const int gi = base + i - 2;
        const int gj = j - 2;
        float v = 0.0f;
        if ((unsigned)gi < (unsigned)HW && (unsigned)gj < (unsigned)HW)
            v = xp[gi * HW + gj];
        float s, c;
        __sincosf(v, &s, &c);
        scs[i][j] = make_float2(c, s);
    }
    __syncthreads();

    // Thread = (column j, segment of 16 output rows). Walk 20 tile rows;
    // at tile row r, variant di feeds pending output i = r - di.
    const int j  = tid & 63;          // 0..63
    const int i0 = (tid >> 6) * 16;   // 0 or 16 (rel. to base)

    float acc[16];

#pragma unroll
    for (int r = 0; r < 20; ++r) {
        const int tr = i0 + r;
        const float2 v0 = scs[tr][j + 0];
        const float2 v1 = scs[tr][j + 1];
        const float2 v2 = scs[tr][j + 2];
        const float2 v3 = scs[tr][j + 3];
        const float2 v4 = scs[tr][j + 4];

#pragma unroll
        for (int di = 0; di < 5; ++di) {
            const int i = r - di;                  // output rel index in segment
            if (i < 0 || i >= 16) continue;
            float h;
            if (di == 0) {
                // p = 0 excluded: only dj = 1..4.
                h = (fmaf(-t[1], v1.y, v1.x) * fmaf(-t[2], v2.y, v2.x))
                  * (fmaf(-t[3], v3.y, v3.x) * fmaf(-t[4], v4.y, v4.x));
            } else {
                const int b = di * 5;
                h = (fmaf(-t[b    ], v0.y, v0.x) * fmaf(-t[b + 1], v1.y, v1.x))
                  * (fmaf(-t[b + 2], v2.y, v2.x) * fmaf(-t[b + 3], v3.y, v3.x));
                h *= fmaf(-t[b + 4], v4.y, v4.x);
            }
            acc[i] = (di == 0) ? h : acc[i] * h;
            if (di == 4)   // output complete -> store, free the register
                op[(base + i0 + i) * HW + j] = acc[i] * scale;
        }
    }
}

extern "C" void kernel_launch(void* const* d_in, const int* in_sizes, int n_in,
                              void* d_out, int out_size)
{
    const float* x = (const float*)d_in[0];
    const float* w = (const float*)d_in[1];
    float* out = (float*)d_out;

    const int planes = in_sizes[0] / PLANE;   // B*C = 512

    prep_kernel<<<1, 32>>>(w);
    quanv_kernel<<<planes * 2, 128>>>(x, out);
}